// round 16
// baseline (speedup 1.0000x reference)
#include <cuda_runtime.h>
#include <math.h>

// BezierRenderer: 16 batches, 512x512, 10 segments. SINGLE kernel, NO barrier,
// NO shared memory. Grid (16,8,16) = 2048 blocks (batch fastest), 256 threads.
// Tile 64x32 px; each thread owns 8 px: float4 at (x,y) and (x,y+16).
// Gaussian weights are COMPILE-TIME constants (LDC.128 per lane, no exp2f).
// Every warp redundantly computes setup; render loop broadcasts segment
// params via __shfl_sync; clamps via FFMA.SAT / __saturatef.

#define NSEG  10
#define SIZEI 512

// W[p][i] = gaus[start_i + p], start = {10,6,3,0},
// gaus[k] = 0.75*exp(-0.125*(k-9.5)^2). Precomputed to float precision.
__constant__ float4 c_W[NSEG] = {
    {0.72692490f, 0.16219875f, 3.8145510e-3f, 9.4556400e-6f},  // p=0
    {0.56613000f, 0.34337475f, 1.7095618e-2f, 8.9709700e-5f},  // p=1
    {0.34337475f, 0.56613000f, 5.9669550e-2f, 6.6287100e-4f},  // p=2
    {0.16219875f, 0.72692490f, 0.16219875f,   3.8145510e-3f},  // p=3
    {0.05966955f, 0.72692490f, 0.34337475f,   1.7095618e-2f},  // p=4
    {0.01709562f, 0.56613000f, 0.56613000f,   5.9669550e-2f},  // p=5
    {3.8145510e-3f, 0.34337475f, 0.72692490f, 0.16219875f},    // p=6
    {6.6287100e-4f, 0.16219875f, 0.72692490f, 0.34337475f},    // p=7
    {8.9709700e-5f, 0.05966955f, 0.56613000f, 0.56613000f},    // p=8
    {9.4556400e-6f, 0.01709562f, 0.34337475f, 0.72692490f},    // p=9
};

__global__ void __launch_bounds__(256)
bezier_kernel(const float* __restrict__ traj,
              const float* __restrict__ thk,
              float* __restrict__ out)
{
    const int b   = blockIdx.x;         // 0..15 (fastest -> decorrelated activity)
    const int tx  = blockIdx.y;         // 0..7   (64 px wide)
    const int ty  = blockIdx.z;         // 0..15  (32 px tall)
    const int tid = threadIdx.x;

    const int x  = (tx << 6) + (tid & 15) * 4;
    const int y0 = (ty << 5) + (tid >> 4);           // rows y0 and y0+16
    float* outp0 = out + ((size_t)b << 18) + ((size_t)y0 << 9) + x;
    float* outp1 = outp0 + 16 * SIZEI;

    // Speculative zero fill — issues immediately, no dependencies.
    const float4 z = make_float4(0.f, 0.f, 0.f, 0.f);
    *reinterpret_cast<float4*>(outp0) = z;
    *reinterpret_cast<float4*>(outp1) = z;

    // ---- per-warp setup (all warps, no barrier, no exp) ----
    const int lane = tid & 31;

    const float4 tyv = __ldg(reinterpret_cast<const float4*>(traj + b * 8));
    const float4 txv = __ldg(reinterpret_cast<const float4*>(traj + b * 8 + 4));
    const float4 tkv = __ldg(reinterpret_cast<const float4*>(thk + b * 4));

    // thick = 2 * sum(thk*2 + 0.5) over 4 ctrl
    const float thick    = ((tkv.x + tkv.y + tkv.z + tkv.w) * 2.f + 2.f) * 2.f;
    const float invthick = __fdividef(1.f, thick);

    // Stroke point for this lane (weights from constant memory).
    float py, px;
    if (lane < NSEG) {
        const float4 w = c_W[lane];
        py = (w.x * tyv.x + w.y * tyv.y + w.z * tyv.z + w.w * tyv.w) * 512.f;
        px = (w.x * txv.x + w.y * txv.y + w.z * txv.z + w.w * txv.w) * 512.f;
    } else {                              // appended last point
        py = tyv.w * 512.f;
        px = txv.w * 512.f;
    }

    // Segment j: point j -> j+1 (from lane j+1 via shfl). Lane j owns seg j.
    const float py1 = __shfl_down_sync(0xFFFFFFFFu, py, 1);
    const float px1 = __shfl_down_sync(0xFFFFFFFFu, px, 1);
    const float dy  = py1 - py;
    const float dx  = px1 - px;
    const float id2 = __fdividef(1.f, dy * dy + dx * dx + 1e-5f);

    // Cull segment `lane` against this 64x32 tile: center
    // (tx*64+31.5, ty*32+15.5); max pixel-to-center distance
    // sqrt(31.5^2+15.5^2) = 35.11 < 35.2.
    const float cx = (float)(tx << 6) + 31.5f;
    const float cy = (float)(ty << 5) + 15.5f;
    const float lim = thick + 35.2f;
    const float ayc = cy - py;
    const float axc = cx - px;
    const float tc  = __saturatef((ayc * dy + axc * dx) * id2);
    const float ryc = fmaf(-tc, dy, ayc);
    const float rxc = fmaf(-tc, dx, axc);
    const bool  act = (lane < NSEG) && (fmaf(ryc, ryc, rxc * rxc) < lim * lim);
    unsigned int mask = __ballot_sync(0xFFFFFFFFu, act);

    if (mask == 0) return;                 // zeros already stored

    const float yf0 = (float)y0;
    const float yf1 = (float)(y0 + 16);
    const float x0  = (float)x;

    float a0 = 1e30f, a1 = 1e30f, a2 = 1e30f, a3 = 1e30f;   // row y0
    float b0 = 1e30f, b1 = 1e30f, b2 = 1e30f, b3 = 1e30f;   // row y0+16

    while (mask) {
        const int j = __ffs((int)mask) - 1;
        mask &= mask - 1;

        // Broadcast segment j's params from lane j.
        const float vjy = __shfl_sync(0xFFFFFFFFu, py, j);
        const float vjx = __shfl_sync(0xFFFFFFFFu, px, j);
        const float djy = __shfl_sync(0xFFFFFFFFu, dy, j);
        const float djx = __shfl_sync(0xFFFFFFFFu, dx, j);
        const float ij  = __shfl_sync(0xFFFFFFFFu, id2, j);

        // t = saturate((pv . d) * ij) = saturate(pvx*e + f[row])
        const float e    = ij * djx;
        const float ayA  = yf0 - vjy;
        const float ayB  = yf1 - vjy;
        const float fA   = ayA * djy * ij;
        const float fB   = ayB * djy * ij;
        const float pvx0 = x0 - vjx;

#pragma unroll
        for (int c = 0; c < 4; c++) {
            const float pvx = pvx0 + (float)c;
            // row A
            {
                float t  = __saturatef(fmaf(pvx, e, fA));   // FFMA.SAT
                float ry = fmaf(-t, djy, ayA);
                float rx = fmaf(-t, djx, pvx);
                float dd = fmaf(ry, ry, rx * rx);
                if (c == 0) a0 = fminf(a0, dd);
                if (c == 1) a1 = fminf(a1, dd);
                if (c == 2) a2 = fminf(a2, dd);
                if (c == 3) a3 = fminf(a3, dd);
            }
            // row B
            {
                float t  = __saturatef(fmaf(pvx, e, fB));
                float ry = fmaf(-t, djy, ayB);
                float rx = fmaf(-t, djx, pvx);
                float dd = fmaf(ry, ry, rx * rx);
                if (c == 0) b0 = fminf(b0, dd);
                if (c == 1) b1 = fminf(b1, dd);
                if (c == 2) b2 = fminf(b2, dd);
                if (c == 3) b3 = fminf(b3, dd);
            }
        }
    }

    float4 r0, r1;
    r0.x = __saturatef((thick - sqrtf(a0)) * invthick);
    r0.y = __saturatef((thick - sqrtf(a1)) * invthick);
    r0.z = __saturatef((thick - sqrtf(a2)) * invthick);
    r0.w = __saturatef((thick - sqrtf(a3)) * invthick);
    r1.x = __saturatef((thick - sqrtf(b0)) * invthick);
    r1.y = __saturatef((thick - sqrtf(b1)) * invthick);
    r1.z = __saturatef((thick - sqrtf(b2)) * invthick);
    r1.w = __saturatef((thick - sqrtf(b3)) * invthick);

    *reinterpret_cast<float4*>(outp0) = r0;
    *reinterpret_cast<float4*>(outp1) = r1;
}

extern "C" void kernel_launch(void* const* d_in, const int* in_sizes, int n_in,
                              void* d_out, int out_size)
{
    const float* traj = (const float*)d_in[0];   // (16, 2, 4)
    const float* thk  = (const float*)d_in[1];   // (16, 1, 4)
    float* out = (float*)d_out;                  // (16, 512, 512)

    dim3 grid(16, 8, 16);                        // 2048 blocks, batch fastest
    bezier_kernel<<<grid, 256>>>(traj, thk, out);
}

// round 17
// speedup vs baseline: 1.0525x; 1.0525x over previous
#include <cuda_runtime.h>
#include <math.h>

// BezierRenderer: 16 batches, 512x512, 10 segments. SINGLE kernel, NO barrier,
// NO shared memory. Grid (16,8,8) = 1024 blocks (batch fastest), 256 threads.
// Block = 64x64 px = TWO independently-culled 64x32 sub-tiles; each thread
// owns 16 px (4 rows x float4). Per-warp setup done ONCE (exp2f weights);
// one ballot per sub-tile; sub-tiles rendered sequentially (8 accumulators
// reused). FFMA.SAT inner loop, shfl-broadcast segment params.

#define NSEG  10
#define SIZEI 512

__device__ __forceinline__ void render_subtile(
    unsigned int mask, float py, float px, float dy, float dx, float id2,
    float thick, float invthick, float yfA, float x0,
    float* outpA, float* outpB)
{
    const float yfB = yfA + 16.f;
    float a0 = 1e30f, a1 = 1e30f, a2 = 1e30f, a3 = 1e30f;   // row A
    float b0 = 1e30f, b1 = 1e30f, b2 = 1e30f, b3 = 1e30f;   // row B

    while (mask) {
        const int j = __ffs((int)mask) - 1;
        mask &= mask - 1;

        // Broadcast segment j's params from lane j.
        const float vjy = __shfl_sync(0xFFFFFFFFu, py, j);
        const float vjx = __shfl_sync(0xFFFFFFFFu, px, j);
        const float djy = __shfl_sync(0xFFFFFFFFu, dy, j);
        const float djx = __shfl_sync(0xFFFFFFFFu, dx, j);
        const float ij  = __shfl_sync(0xFFFFFFFFu, id2, j);

        // t = saturate((pv . d) * ij) = saturate(pvx*e + f[row])
        const float e    = ij * djx;
        const float ayA  = yfA - vjy;
        const float ayB  = yfB - vjy;
        const float fA   = ayA * djy * ij;
        const float fB   = ayB * djy * ij;
        const float pvx0 = x0 - vjx;

#pragma unroll
        for (int c = 0; c < 4; c++) {
            const float pvx = pvx0 + (float)c;
            {
                float t  = __saturatef(fmaf(pvx, e, fA));   // FFMA.SAT
                float ry = fmaf(-t, djy, ayA);
                float rx = fmaf(-t, djx, pvx);
                float dd = fmaf(ry, ry, rx * rx);
                if (c == 0) a0 = fminf(a0, dd);
                if (c == 1) a1 = fminf(a1, dd);
                if (c == 2) a2 = fminf(a2, dd);
                if (c == 3) a3 = fminf(a3, dd);
            }
            {
                float t  = __saturatef(fmaf(pvx, e, fB));
                float ry = fmaf(-t, djy, ayB);
                float rx = fmaf(-t, djx, pvx);
                float dd = fmaf(ry, ry, rx * rx);
                if (c == 0) b0 = fminf(b0, dd);
                if (c == 1) b1 = fminf(b1, dd);
                if (c == 2) b2 = fminf(b2, dd);
                if (c == 3) b3 = fminf(b3, dd);
            }
        }
    }

    float4 r0, r1;
    r0.x = __saturatef((thick - sqrtf(a0)) * invthick);
    r0.y = __saturatef((thick - sqrtf(a1)) * invthick);
    r0.z = __saturatef((thick - sqrtf(a2)) * invthick);
    r0.w = __saturatef((thick - sqrtf(a3)) * invthick);
    r1.x = __saturatef((thick - sqrtf(b0)) * invthick);
    r1.y = __saturatef((thick - sqrtf(b1)) * invthick);
    r1.z = __saturatef((thick - sqrtf(b2)) * invthick);
    r1.w = __saturatef((thick - sqrtf(b3)) * invthick);

    *reinterpret_cast<float4*>(outpA) = r0;
    *reinterpret_cast<float4*>(outpB) = r1;
}

__global__ void __launch_bounds__(256)
bezier_kernel(const float* __restrict__ traj,
              const float* __restrict__ thk,
              float* __restrict__ out)
{
    const int b   = blockIdx.x;         // 0..15 (fastest -> decorrelated activity)
    const int tx  = blockIdx.y;         // 0..7  (64 px wide)
    const int tyb = blockIdx.z;         // 0..7  (64 px tall)
    const int tid = threadIdx.x;

    const int x  = (tx << 6) + (tid & 15) * 4;
    const int y0 = (tyb << 6) + (tid >> 4);          // rows y0,+16,+32,+48
    float* outp0 = out + ((size_t)b << 18) + ((size_t)y0 << 9) + x;
    float* outp1 = outp0 + 16 * SIZEI;
    float* outp2 = outp0 + 32 * SIZEI;
    float* outp3 = outp0 + 48 * SIZEI;

    // Speculative zero fill — issues immediately, no dependencies.
    const float4 z = make_float4(0.f, 0.f, 0.f, 0.f);
    *reinterpret_cast<float4*>(outp0) = z;
    *reinterpret_cast<float4*>(outp1) = z;
    *reinterpret_cast<float4*>(outp2) = z;
    *reinterpret_cast<float4*>(outp3) = z;

    // ---- per-warp setup (all warps, no barrier) ----
    const int lane = tid & 31;

    const float4 tyv = __ldg(reinterpret_cast<const float4*>(traj + b * 8));
    const float4 txv = __ldg(reinterpret_cast<const float4*>(traj + b * 8 + 4));
    const float4 tkv = __ldg(reinterpret_cast<const float4*>(thk + b * 4));

    // thick = 2 * sum(thk*2 + 0.5) over 4 ctrl
    const float thick    = ((tkv.x + tkv.y + tkv.z + tkv.w) * 2.f + 2.f) * 2.f;
    const float invthick = 1.f / thick;

    // Stroke point for this lane. Lanes 0..9: gaussian-weighted sample,
    // W[p][i] = 0.75*exp(-0.125*n_i^2), n_i = p - {-0.5,3.5,6.5,9.5};
    // exp(-0.125 n^2) == exp2(-0.18033688 n^2) -> MUFU.EX2.
    float py, px;
    if (lane < NSEG) {
        const float p  = (float)lane;
        const float n0 = p + 0.5f, n1 = p - 3.5f, n2 = p - 6.5f, n3 = p - 9.5f;
        const float C  = -0.18033688f;    // -0.125 * log2(e)
        const float w0 = 0.75f * exp2f(C * n0 * n0);
        const float w1 = 0.75f * exp2f(C * n1 * n1);
        const float w2 = 0.75f * exp2f(C * n2 * n2);
        const float w3 = 0.75f * exp2f(C * n3 * n3);
        py = (w0 * tyv.x + w1 * tyv.y + w2 * tyv.z + w3 * tyv.w) * 512.f;
        px = (w0 * txv.x + w1 * txv.y + w2 * txv.z + w3 * txv.w) * 512.f;
    } else {                              // appended last point
        py = tyv.w * 512.f;
        px = txv.w * 512.f;
    }

    // Segment j: point j -> j+1 (from lane j+1 via shfl). Lane j owns seg j.
    const float py1 = __shfl_down_sync(0xFFFFFFFFu, py, 1);
    const float px1 = __shfl_down_sync(0xFFFFFFFFu, px, 1);
    const float dy  = py1 - py;
    const float dx  = px1 - px;
    const float id2 = 1.f / (dy * dy + dx * dx + 1e-5f);

    // Cull segment `lane` against both 64x32 sub-tiles. Centers
    // (tx*64+31.5, tyb*64+15.5) and (tx*64+31.5, tyb*64+47.5); max
    // pixel-to-center distance sqrt(31.5^2+15.5^2) = 35.11 < 35.2.
    const float cx   = (float)(tx << 6) + 31.5f;
    const float cy0  = (float)(tyb << 6) + 15.5f;
    const float cy1  = cy0 + 32.f;
    const float lim  = thick + 35.2f;
    const float lim2 = lim * lim;
    const float axc  = cx - px;

    bool act0 = false, act1 = false;
    if (lane < NSEG) {
        {
            const float ayc = cy0 - py;
            const float t   = __saturatef((ayc * dy + axc * dx) * id2);
            const float ry  = fmaf(-t, dy, ayc);
            const float rx  = fmaf(-t, dx, axc);
            act0 = fmaf(ry, ry, rx * rx) < lim2;
        }
        {
            const float ayc = cy1 - py;
            const float t   = __saturatef((ayc * dy + axc * dx) * id2);
            const float ry  = fmaf(-t, dy, ayc);
            const float rx  = fmaf(-t, dx, axc);
            act1 = fmaf(ry, ry, rx * rx) < lim2;
        }
    }
    const unsigned int mask0 = __ballot_sync(0xFFFFFFFFu, act0);
    const unsigned int mask1 = __ballot_sync(0xFFFFFFFFu, act1);

    if ((mask0 | mask1) == 0) return;      // zeros already stored

    const float x0 = (float)x;

    if (mask0)
        render_subtile(mask0, py, px, dy, dx, id2, thick, invthick,
                       (float)y0, x0, outp0, outp1);
    if (mask1)
        render_subtile(mask1, py, px, dy, dx, id2, thick, invthick,
                       (float)(y0 + 32), x0, outp2, outp3);
}

extern "C" void kernel_launch(void* const* d_in, const int* in_sizes, int n_in,
                              void* d_out, int out_size)
{
    const float* traj = (const float*)d_in[0];   // (16, 2, 4)
    const float* thk  = (const float*)d_in[1];   // (16, 1, 4)
    float* out = (float*)d_out;                  // (16, 512, 512)

    dim3 grid(16, 8, 8);                         // 1024 blocks, batch fastest
    bezier_kernel<<<grid, 256>>>(traj, thk, out);
}